// round 3
// baseline (speedup 1.0000x reference)
#include <cuda_runtime.h>
#include <math.h>

#define BB   2
#define NN   512
#define CC   256
#define OUTD 256
#define HH   4
#define HD   64
#define ROWS (BB*NN)   // 1024

// ---- scratch (device globals; no allocation allowed) ----
__device__ float g_hi[ROWS*OUTD];
__device__ float g_hj[ROWS*OUTD];
__device__ float g_v [ROWS*OUTD];
__device__ float g_s1i[ROWS];
__device__ float g_s2i[ROWS];
__device__ float g_s1j[ROWS];
__device__ float g_s2j[ROWS];
__device__ float g_logT[BB*HH*NN*NN];   // [b*4+h][i][j], 8 MB
__device__ float g_mid[ROWS*OUTD];

// ---------------- packed f32x2 helpers (Blackwell) ----------------
typedef unsigned long long u64;

__device__ __forceinline__ u64 pk2(float lo, float hi) {
    u64 r; asm("mov.b64 %0,{%1,%2};" : "=l"(r) : "f"(lo), "f"(hi)); return r;
}
__device__ __forceinline__ u64 splat(float x) {
    u64 r; asm("mov.b64 %0,{%1,%1};" : "=l"(r) : "f"(x)); return r;
}
__device__ __forceinline__ void upk(u64 a, float& x, float& y) {
    asm("mov.b64 {%0,%1},%2;" : "=f"(x), "=f"(y) : "l"(a));
}
__device__ __forceinline__ u64 f2add(u64 a, u64 b) {
    u64 d; asm("add.rn.f32x2 %0,%1,%2;" : "=l"(d) : "l"(a), "l"(b)); return d;
}
__device__ __forceinline__ u64 f2mul(u64 a, u64 b) {
    u64 d; asm("mul.rn.f32x2 %0,%1,%2;" : "=l"(d) : "l"(a), "l"(b)); return d;
}
__device__ __forceinline__ u64 f2fma(u64 a, u64 b, u64 c) {
    u64 d; asm("fma.rn.f32x2 %0,%1,%2,%3;" : "=l"(d) : "l"(a), "l"(b), "l"(c)); return d;
}
__device__ __forceinline__ float tanha(float x) {
    float r; asm("tanh.approx.f32 %0,%1;" : "=f"(r) : "f"(x)); return r;
}
__device__ __forceinline__ float ex2a(float x) {
    float r; asm("ex2.approx.f32 %0,%1;" : "=f"(r) : "f"(x)); return r;
}

// ============================================================
// K1: h_i = x@We[:C]+be ; h_j = x@We[C:] ; v = x@Wv+bv
//     + per-row sum / sumsq for h_i, h_j
// grid (64, 3), block 256
// ============================================================
__global__ __launch_bounds__(256) void k1_proj(
    const float* __restrict__ x, const float* __restrict__ We,
    const float* __restrict__ be, const float* __restrict__ Wv,
    const float* __restrict__ bv)
{
    __shared__ float sx[16][257];
    int row0 = blockIdx.x * 16;
    int mat  = blockIdx.y;

    for (int t = threadIdx.x; t < 16*256; t += 256)
        sx[t >> 8][t & 255] = x[row0*256 + t];
    __syncthreads();

    int col = threadIdx.x;
    const float* W; float bias; float* out;
    if (mat == 0)      { W = We;           bias = be[col]; out = g_hi; }
    else if (mat == 1) { W = We + 256*256; bias = 0.f;     out = g_hj; }
    else               { W = Wv;           bias = bv[col]; out = g_v;  }

    float acc[16];
    #pragma unroll
    for (int r = 0; r < 16; r++) acc[r] = bias;

    for (int k = 0; k < 256; k++) {
        float w = W[k*256 + col];
        #pragma unroll
        for (int r = 0; r < 16; r++) acc[r] = fmaf(sx[r][k], w, acc[r]);
    }
    #pragma unroll
    for (int r = 0; r < 16; r++) out[(row0 + r)*256 + col] = acc[r];

    if (mat < 2) {
        __syncthreads();
        #pragma unroll
        for (int r = 0; r < 16; r++) sx[r][col] = acc[r];
        __syncthreads();
        int wid = threadIdx.x >> 5, lane = threadIdx.x & 31;
        float* s1 = (mat == 0) ? g_s1i : g_s1j;
        float* s2 = (mat == 0) ? g_s2i : g_s2j;
        for (int r = wid; r < 16; r += 8) {
            float a = 0.f, q = 0.f;
            for (int c = lane; c < 256; c += 32) {
                float v = sx[r][c]; a += v; q = fmaf(v, v, q);
            }
            #pragma unroll
            for (int off = 16; off; off >>= 1) {
                a += __shfl_xor_sync(0xffffffffu, a, off);
                q += __shfl_xor_sync(0xffffffffu, q, off);
            }
            if (lane == 0) { s1[row0 + r] = a; s2[row0 + r] = q; }
        }
    }
}

// ============================================================
// K2: dominant pairwise kernel.
//   LN stats factored; GELU via tanh approximation (HW MUFU.TANH).
//   __launch_bounds__(256,2) -> 2 blocks/SM -> 4 warps/SMSP.
// grid (128, 4), block 256; warp = 1 i-row x 32 j-rows
// ============================================================
#define TI 8
#define SJ 258   // 8B-aligned row stride, conflict-free LDS.64 per 16-lane phase

__global__ void __launch_bounds__(256, 2) k2_pair(
    const float* __restrict__ ln1g, const float* __restrict__ ln1b,
    const float* __restrict__ W2,   const float* __restrict__ b2)
{
    __shared__ float shi[TI][SJ];
    __shared__ float shj[32][SJ];
    __shared__ ulonglong2 sGB[128];            // {(g0,g1),(b0,b1)} per ch-pair
    __shared__ ulonglong2 sWa[128], sWb[128];  // head 0/1 and 2/3 weight packs
    __shared__ float s1i[TI], s2i[TI], s1j[32], s2j[32], sb2[4];

    int ri0 = blockIdx.x * TI;
    int b   = ri0 >> 9;
    int ib0 = ri0 & 511;
    int tid = threadIdx.x;

    for (int t = tid; t < TI*256; t += 256)
        shi[t >> 8][t & 255] = g_hi[ri0*256 + t];
    if (tid < 128) {
        float g0 = ln1g[2*tid], g1 = ln1g[2*tid+1];
        float b0 = ln1b[2*tid], b1 = ln1b[2*tid+1];
        sGB[tid].x = pk2(g0, g1);
        sGB[tid].y = pk2(b0, b1);
        const float* w = W2 + tid*8;   // rows 2t, 2t+1 x 4 heads
        sWa[tid].x = pk2(w[0], w[4]);
        sWa[tid].y = pk2(w[1], w[5]);
        sWb[tid].x = pk2(w[2], w[6]);
        sWb[tid].y = pk2(w[3], w[7]);
    }
    if (tid < TI) { s1i[tid] = g_s1i[ri0 + tid]; s2i[tid] = g_s2i[ri0 + tid]; }
    if (tid < 4)  sb2[tid] = b2[tid];

    int ti = tid >> 5;
    int tj = tid & 31;

    const u64 HALF = splat(0.5f);
    const u64 C0   = splat(0.7978845608028654f);
    const u64 C3   = splat(0.7978845608028654f * 0.044715f);

    for (int jt = 0; jt < 4; jt++) {
        int j0  = blockIdx.y * 128 + jt * 32;
        int rj0 = b * NN + j0;
        __syncthreads();
        for (int t = tid; t < 32*256; t += 256)
            shj[t >> 8][t & 255] = g_hj[rj0*256 + t];
        if (tid < 32) { s1j[tid] = g_s1j[rj0 + tid]; s2j[tid] = g_s2j[rj0 + tid]; }
        __syncthreads();

        // pass A: packed dot(h_i, h_j) for the Var cross term
        u64 dac = splat(0.f);
        #pragma unroll 8
        for (int c2 = 0; c2 < 128; c2++) {
            u64 a = *(const u64*)&shi[ti][2*c2];
            u64 c = *(const u64*)&shj[tj][2*c2];
            dac = f2fma(a, c, dac);
        }
        float dlo, dhi; upk(dac, dlo, dhi);
        float dot = dlo + dhi;

        float mu   = (s1i[ti] + s1j[tj]) * (1.f/256.f);
        float ex2  = (s2i[ti] + s2j[tj] + 2.f*dot) * (1.f/256.f);
        float var  = ex2 - mu*mu;
        float rstd = rsqrtf(var + 1e-5f);
        u64 rstd2 = splat(rstd);
        u64 nmr2  = splat(-mu * rstd);

        u64 acc0 = splat(0.f), acc1 = splat(0.f), acc2 = splat(0.f), acc3 = splat(0.f);
        #pragma unroll 4
        for (int c2 = 0; c2 < 128; c2++) {
            u64 hiv = *(const u64*)&shi[ti][2*c2];
            u64 hjv = *(const u64*)&shj[tj][2*c2];
            u64 e = f2add(hiv, hjv);
            u64 z = f2fma(e, rstd2, nmr2);
            ulonglong2 gb = sGB[c2];
            u64 y = f2fma(z, gb.x, gb.y);

            // gelu_tanh(y) = 0.5*y*(1 + tanh(0.79788456*(y + 0.044715*y^3)))
            u64 y2 = f2mul(y, y);
            u64 t1 = f2fma(y2, C3, C0);
            u64 ar = f2mul(y, t1);
            float al, ah; upk(ar, al, ah);
            u64 th = pk2(tanha(al), tanha(ah));
            u64 u  = f2mul(y, HALF);
            u64 g  = f2fma(u, th, u);

            ulonglong2 wa = sWa[c2];
            ulonglong2 wb = sWb[c2];
            acc0 = f2fma(g, wa.x, acc0);
            acc1 = f2fma(g, wa.y, acc1);
            acc2 = f2fma(g, wb.x, acc2);
            acc3 = f2fma(g, wb.y, acc3);
        }
        float x0, x1, y0, y1, z0, z1, w0, w1;
        upk(acc0, x0, x1); upk(acc1, y0, y1);
        upk(acc2, z0, z1); upk(acc3, w0, w1);

        // transposed per-head planes: [b*4+h][i][j]; coalesced 128B per warp
        size_t base = ((size_t)(b*4)*NN + (ib0 + ti))*NN + (j0 + tj);
        g_logT[base           ] = x0 + x1 + sb2[0];
        g_logT[base + 262144  ] = y0 + y1 + sb2[1];
        g_logT[base + 524288  ] = z0 + z1 + sb2[2];
        g_logT[base + 786432  ] = w0 + w1 + sb2[3];
    }
}

// ============================================================
// K34: fused softmax + adj@v.
// block = (b,h, 16 i-rows): softmax 16 rows in smem, then
// out[16,64] = adj[16,512] @ v[512,64] streaming 64-j v chunks.
// grid (32, 8), block 256, 48KB dynamic smem.
// ============================================================
__global__ __launch_bounds__(256) void k34_smax_av()
{
    extern __shared__ float dsm[];
    float* sadj = dsm;              // 16 x 512
    float* sv   = dsm + 16*512;     // 64 x 64

    int bh = blockIdx.y; int b = bh >> 2, h = bh & 3;
    int i0 = blockIdx.x * 16;
    int tid = threadIdx.x, w = tid >> 5, lane = tid & 31;

    // phase 1: softmax, 2 rows per warp
    #pragma unroll
    for (int rr = 0; rr < 2; rr++) {
        int r = w*2 + rr;
        const float4* p = (const float4*)(g_logT + ((size_t)bh*NN + i0 + r)*NN);
        float4 v[4];
        float m = -1e30f;
        #pragma unroll
        for (int u = 0; u < 4; u++) {
            v[u] = p[lane + 32*u];
            m = fmaxf(m, fmaxf(fmaxf(v[u].x, v[u].y), fmaxf(v[u].z, v[u].w)));
        }
        #pragma unroll
        for (int off = 16; off; off >>= 1)
            m = fmaxf(m, __shfl_xor_sync(0xffffffffu, m, off));
        float s = 0.f;
        #pragma unroll
        for (int u = 0; u < 4; u++) {
            v[u].x = ex2a((v[u].x - m)*1.44269504f);
            v[u].y = ex2a((v[u].y - m)*1.44269504f);
            v[u].z = ex2a((v[u].z - m)*1.44269504f);
            v[u].w = ex2a((v[u].w - m)*1.44269504f);
            s += v[u].x + v[u].y + v[u].z + v[u].w;
        }
        #pragma unroll
        for (int off = 16; off; off >>= 1)
            s += __shfl_xor_sync(0xffffffffu, s, off);
        float inv = 1.f / s;
        float4* q = (float4*)&sadj[r*512];
        #pragma unroll
        for (int u = 0; u < 4; u++) {
            v[u].x *= inv; v[u].y *= inv; v[u].z *= inv; v[u].w *= inv;
            q[lane + 32*u] = v[u];
        }
    }
    __syncthreads();

    // phase 2: 16x512 @ 512x64
    int ty = tid >> 4, tx = tid & 15;
    float a0 = 0.f, a1 = 0.f, a2 = 0.f, a3 = 0.f;
    for (int j0 = 0; j0 < NN; j0 += 64) {
        for (int t = tid; t < 1024; t += 256) {
            int r = t >> 4, c = (t & 15) * 4;
            *(float4*)&sv[r*64 + c] =
                *(const float4*)&g_v[((size_t)(b*NN + j0 + r))*256 + h*64 + c];
        }
        __syncthreads();
        #pragma unroll 8
        for (int j = 0; j < 64; j++) {
            float a = sadj[ty*512 + j0 + j];
            float4 v4 = *(const float4*)&sv[j*64 + tx*4];
            a0 = fmaf(a, v4.x, a0);
            a1 = fmaf(a, v4.y, a1);
            a2 = fmaf(a, v4.z, a2);
            a3 = fmaf(a, v4.w, a3);
        }
        __syncthreads();
    }
    float* o = g_mid + ((size_t)(b*NN + i0 + ty))*256 + h*64 + tx*4;
    o[0] = a0; o[1] = a1; o[2] = a2; o[3] = a3;
}

// ============================================================
// K5: out = LN2( mid@Wo + bo + x )
// grid 128 (8 rows each), block 256
// ============================================================
__global__ __launch_bounds__(256) void k5_out(
    const float* __restrict__ x,  const float* __restrict__ Wo,
    const float* __restrict__ bo, const float* __restrict__ g2,
    const float* __restrict__ bt, float* __restrict__ out)
{
    __shared__ float sm[8][257];
    __shared__ float smu[8], srs[8];
    int row0 = blockIdx.x * 8;
    int tid  = threadIdx.x;

    for (int t = tid; t < 8*256; t += 256)
        sm[t >> 8][t & 255] = g_mid[row0*256 + t];
    __syncthreads();

    int col = tid;
    float acc[8];
    #pragma unroll
    for (int r = 0; r < 8; r++) acc[r] = bo[col];
    for (int k = 0; k < 256; k++) {
        float w = Wo[k*256 + col];
        #pragma unroll
        for (int r = 0; r < 8; r++) acc[r] = fmaf(sm[r][k], w, acc[r]);
    }
    #pragma unroll
    for (int r = 0; r < 8; r++) acc[r] += x[(row0 + r)*256 + col];
    __syncthreads();
    #pragma unroll
    for (int r = 0; r < 8; r++) sm[r][col] = acc[r];
    __syncthreads();

    int wid = tid >> 5, lane = tid & 31;
    {
        float a = 0.f, q = 0.f;
        for (int c = lane; c < 256; c += 32) {
            float v = sm[wid][c]; a += v; q = fmaf(v, v, q);
        }
        #pragma unroll
        for (int off = 16; off; off >>= 1) {
            a += __shfl_xor_sync(0xffffffffu, a, off);
            q += __shfl_xor_sync(0xffffffffu, q, off);
        }
        if (lane == 0) {
            float mu = a * (1.f/256.f);
            float var = q * (1.f/256.f) - mu*mu;
            smu[wid] = mu; srs[wid] = rsqrtf(var + 1e-5f);
        }
    }
    __syncthreads();
    float g = g2[col], bb = bt[col];
    #pragma unroll
    for (int r = 0; r < 8; r++)
        out[(row0 + r)*256 + col] = (sm[r][col] - smu[r]) * srs[r] * g + bb;
}

// ============================================================
extern "C" void kernel_launch(void* const* d_in, const int* in_sizes, int n_in,
                              void* d_out, int out_size)
{
    const float* x    = (const float*)d_in[0];
    const float* We   = (const float*)d_in[1];
    const float* be   = (const float*)d_in[2];
    const float* ln1g = (const float*)d_in[3];
    const float* ln1b = (const float*)d_in[4];
    const float* W2   = (const float*)d_in[5];
    const float* b2   = (const float*)d_in[6];
    const float* Wv   = (const float*)d_in[7];
    const float* bv   = (const float*)d_in[8];
    const float* Wo   = (const float*)d_in[9];
    const float* bo   = (const float*)d_in[10];
    const float* ln2g = (const float*)d_in[11];
    const float* ln2b = (const float*)d_in[12];
    float* out = (float*)d_out;

    k1_proj    <<<dim3(64, 3),  256>>>(x, We, be, Wv, bv);
    k2_pair    <<<dim3(128, 4), 256>>>(ln1g, ln1b, W2, b2);
    k34_smax_av<<<dim3(32, 8),  256, 49152>>>();
    k5_out     <<<128,          256>>>(x, Wo, bo, ln2g, ln2b, out);
}

// round 4
// speedup vs baseline: 1.6427x; 1.6427x over previous
#include <cuda_runtime.h>
#include <math.h>

#define BB   2
#define NN   512
#define CC   256
#define OUTD 256
#define HH   4
#define HD   64
#define ROWS (BB*NN)   // 1024

// ---- scratch (device globals; no allocation allowed) ----
__device__ float g_hi[ROWS*OUTD];
__device__ float g_hj[ROWS*OUTD];
__device__ float g_v [ROWS*OUTD];
__device__ float g_s1i[ROWS];
__device__ float g_s2i[ROWS];
__device__ float g_s1j[ROWS];
__device__ float g_s2j[ROWS];
__device__ float g_logits[ROWS*NN*HH];          // [ri][j][h], 8 MB
__device__ float g_adjT[BB*HH*NN*NN];           // [b*4+h][i][j], 8 MB
__device__ float g_mid[ROWS*OUTD];

// ---------------- packed f32x2 helpers (Blackwell) ----------------
typedef unsigned long long u64;

__device__ __forceinline__ u64 pk2(float lo, float hi) {
    u64 r; asm("mov.b64 %0,{%1,%2};" : "=l"(r) : "f"(lo), "f"(hi)); return r;
}
__device__ __forceinline__ u64 splat(float x) {
    u64 r; asm("mov.b64 %0,{%1,%1};" : "=l"(r) : "f"(x)); return r;
}
__device__ __forceinline__ void upk(u64 a, float& x, float& y) {
    asm("mov.b64 {%0,%1},%2;" : "=f"(x), "=f"(y) : "l"(a));
}
__device__ __forceinline__ u64 f2add(u64 a, u64 b) {
    u64 d; asm("add.rn.f32x2 %0,%1,%2;" : "=l"(d) : "l"(a), "l"(b)); return d;
}
__device__ __forceinline__ u64 f2mul(u64 a, u64 b) {
    u64 d; asm("mul.rn.f32x2 %0,%1,%2;" : "=l"(d) : "l"(a), "l"(b)); return d;
}
__device__ __forceinline__ u64 f2fma(u64 a, u64 b, u64 c) {
    u64 d; asm("fma.rn.f32x2 %0,%1,%2,%3;" : "=l"(d) : "l"(a), "l"(b), "l"(c)); return d;
}
__device__ __forceinline__ float tanha(float x) {
    float r; asm("tanh.approx.f32 %0,%1;" : "=f"(r) : "f"(x)); return r;
}

// ============================================================
// K1: h_i = x@We[:C]+be ; h_j = x@We[C:] ; v = x@Wv+bv
//     + per-row sum / sumsq for h_i, h_j
// grid (64, 3), block 256.
// Inner loop: float4 smem reads + 8-deep W prefetch (MLP=8).
// ============================================================
__global__ __launch_bounds__(256) void k1_proj(
    const float* __restrict__ x, const float* __restrict__ We,
    const float* __restrict__ be, const float* __restrict__ Wv,
    const float* __restrict__ bv)
{
    __shared__ float sx[16][260];
    int row0 = blockIdx.x * 16;
    int mat  = blockIdx.y;

    for (int t = threadIdx.x; t < 16*256; t += 256)
        sx[t >> 8][t & 255] = x[row0*256 + t];
    __syncthreads();

    int col = threadIdx.x;
    const float* W; float bias; float* out;
    if (mat == 0)      { W = We;           bias = be[col]; out = g_hi; }
    else if (mat == 1) { W = We + 256*256; bias = 0.f;     out = g_hj; }
    else               { W = Wv;           bias = bv[col]; out = g_v;  }

    float acc[16];
    #pragma unroll
    for (int r = 0; r < 16; r++) acc[r] = bias;

    const float* Wp = W + col;
    float w[8], wn[8];
    #pragma unroll
    for (int u = 0; u < 8; u++) w[u] = Wp[u*256];

    for (int k = 0; k < 256; k += 8) {
        int kn = (k + 8) & 255;   // wraps to 0 on last iter (value unused)
        #pragma unroll
        for (int u = 0; u < 8; u++) wn[u] = Wp[(kn + u)*256];
        #pragma unroll
        for (int r = 0; r < 16; r++) {
            float4 xa = *(const float4*)&sx[r][k];
            float4 xb = *(const float4*)&sx[r][k+4];
            float a = acc[r];
            a = fmaf(xa.x, w[0], a); a = fmaf(xa.y, w[1], a);
            a = fmaf(xa.z, w[2], a); a = fmaf(xa.w, w[3], a);
            a = fmaf(xb.x, w[4], a); a = fmaf(xb.y, w[5], a);
            a = fmaf(xb.z, w[6], a); a = fmaf(xb.w, w[7], a);
            acc[r] = a;
        }
        #pragma unroll
        for (int u = 0; u < 8; u++) w[u] = wn[u];
    }
    #pragma unroll
    for (int r = 0; r < 16; r++) out[(row0 + r)*256 + col] = acc[r];

    if (mat < 2) {
        __syncthreads();
        #pragma unroll
        for (int r = 0; r < 16; r++) sx[r][col] = acc[r];
        __syncthreads();
        int wid = threadIdx.x >> 5, lane = threadIdx.x & 31;
        float* s1 = (mat == 0) ? g_s1i : g_s1j;
        float* s2 = (mat == 0) ? g_s2i : g_s2j;
        for (int r = wid; r < 16; r += 8) {
            float a = 0.f, q = 0.f;
            for (int c = lane; c < 256; c += 32) {
                float v = sx[r][c]; a += v; q = fmaf(v, v, q);
            }
            #pragma unroll
            for (int off = 16; off; off >>= 1) {
                a += __shfl_xor_sync(0xffffffffu, a, off);
                q += __shfl_xor_sync(0xffffffffu, q, off);
            }
            if (lane == 0) { s1[row0 + r] = a; s2[row0 + r] = q; }
        }
    }
}

// ============================================================
// K2: dominant pairwise kernel, f32x2-packed over channel pairs.
//   LN stats factored; GELU via tanh approximation (HW MUFU.TANH).
// grid (128, 4), block 256; warp = 1 i-row x 32 j-rows
// ============================================================
#define TI 8
#define SJ 258   // 8B-aligned row stride

__global__ __launch_bounds__(256) void k2_pair(
    const float* __restrict__ ln1g, const float* __restrict__ ln1b,
    const float* __restrict__ W2,   const float* __restrict__ b2)
{
    __shared__ float shi[TI][SJ];
    __shared__ float shj[32][SJ];
    __shared__ ulonglong2 sGB[128];            // {(g0,g1),(b0,b1)} per ch-pair
    __shared__ float4 sWa[128], sWb[128];      // h01 / h23 channel-pair packs
    __shared__ float s1i[TI], s2i[TI], s1j[32], s2j[32];
    __shared__ float sb2[4];

    int ri0 = blockIdx.x * TI;
    int b   = ri0 / NN;
    int tid = threadIdx.x;

    for (int t = tid; t < TI*256; t += 256)
        shi[t >> 8][t & 255] = g_hi[ri0*256 + t];
    if (tid < 128) {
        sGB[tid].x = pk2(ln1g[2*tid], ln1g[2*tid+1]);
        sGB[tid].y = pk2(ln1b[2*tid], ln1b[2*tid+1]);
        const float* w = W2 + tid*8;   // channels 2t,2t+1 x 4 heads
        sWa[tid] = make_float4(w[0], w[4], w[1], w[5]);
        sWb[tid] = make_float4(w[2], w[6], w[3], w[7]);
    }
    if (tid < TI) { s1i[tid] = g_s1i[ri0 + tid]; s2i[tid] = g_s2i[ri0 + tid]; }
    if (tid < 4)  sb2[tid] = b2[tid];

    int ti = tid >> 5;
    int tj = tid & 31;

    const u64 HALF = splat(0.5f);
    const u64 C0   = splat(0.7978845608028654f);
    const u64 C3   = splat(0.7978845608028654f * 0.044715f);

    for (int jt = 0; jt < 4; jt++) {
        int j0  = blockIdx.y * 128 + jt * 32;
        int rj0 = b * NN + j0;
        __syncthreads();
        for (int t = tid; t < 32*256; t += 256)
            shj[t >> 8][t & 255] = g_hj[rj0*256 + t];
        if (tid < 32) { s1j[tid] = g_s1j[rj0 + tid]; s2j[tid] = g_s2j[rj0 + tid]; }
        __syncthreads();

        // pass A: packed dot(h_i, h_j) for the Var cross term
        u64 dac = splat(0.f);
        #pragma unroll 8
        for (int c2 = 0; c2 < 128; c2++) {
            u64 a = *(const u64*)&shi[ti][2*c2];
            u64 c = *(const u64*)&shj[tj][2*c2];
            dac = f2fma(a, c, dac);
        }
        float dlo, dhi; upk(dac, dlo, dhi);
        float dot = dlo + dhi;

        float mu   = (s1i[ti] + s1j[tj]) * (1.f/256.f);
        float ex2  = (s2i[ti] + s2j[tj] + 2.f*dot) * (1.f/256.f);
        float var  = ex2 - mu*mu;
        float rstd = rsqrtf(var + 1e-5f);
        u64 rstd2 = splat(rstd);
        u64 nmr2  = splat(-mu * rstd);

        u64 acc0 = splat(0.f), acc1 = splat(0.f), acc2 = splat(0.f), acc3 = splat(0.f);
        #pragma unroll 4
        for (int c2 = 0; c2 < 128; c2++) {
            u64 hiv = *(const u64*)&shi[ti][2*c2];
            u64 hjv = *(const u64*)&shj[tj][2*c2];
            u64 e = f2add(hiv, hjv);
            u64 z = f2fma(e, rstd2, nmr2);
            ulonglong2 gb = sGB[c2];
            u64 y = f2fma(z, gb.x, gb.y);

            // gelu_tanh(y) = 0.5*y*(1 + tanh(0.79788456*(y + 0.044715*y^3)))
            u64 y2 = f2mul(y, y);
            u64 t1 = f2fma(y2, C3, C0);
            u64 ar = f2mul(y, t1);
            float al, ah; upk(ar, al, ah);
            u64 th = pk2(tanha(al), tanha(ah));
            u64 u  = f2mul(y, HALF);
            u64 g  = f2fma(u, th, u);

            float4 wa = sWa[c2];
            float4 wb = sWb[c2];
            acc0 = f2fma(g, pk2(wa.x, wa.y), acc0);
            acc1 = f2fma(g, pk2(wa.z, wa.w), acc1);
            acc2 = f2fma(g, pk2(wb.x, wb.y), acc2);
            acc3 = f2fma(g, pk2(wb.z, wb.w), acc3);
        }
        float x0, x1, y0, y1, z0, z1, w0, w1;
        upk(acc0, x0, x1); upk(acc1, y0, y1);
        upk(acc2, z0, z1); upk(acc3, w0, w1);
        ((float4*)g_logits)[(ri0 + ti)*NN + (j0 + tj)] =
            make_float4(x0 + x1 + sb2[0], y0 + y1 + sb2[1],
                        z0 + z1 + sb2[2], w0 + w1 + sb2[3]);
    }
}

// ============================================================
// K3: softmax over j per (b,i,h); writes TRANSPOSED adj [b,h,i,j]
// grid 512, block 256 (8 warps; warp per (ri,h) row)
// ============================================================
__global__ __launch_bounds__(256) void k3_softmax()
{
    int row  = blockIdx.x * 8 + (threadIdx.x >> 5);  // 0..4095
    int lane = threadIdx.x & 31;
    int ri = row >> 2, h = row & 3;
    const float* p = g_logits + (size_t)ri*NN*4 + h;
    int b = ri >> 9, i = ri & 511;
    float* q = g_adjT + ((size_t)(b*4 + h)*NN + i)*NN;

    float vals[16];
    float m = -1e30f;
    #pragma unroll
    for (int k = 0; k < 16; k++) {
        vals[k] = p[(lane + 32*k)*4];
        m = fmaxf(m, vals[k]);
    }
    #pragma unroll
    for (int off = 16; off; off >>= 1)
        m = fmaxf(m, __shfl_xor_sync(0xffffffffu, m, off));
    float s = 0.f;
    #pragma unroll
    for (int k = 0; k < 16; k++) { vals[k] = __expf(vals[k] - m); s += vals[k]; }
    #pragma unroll
    for (int off = 16; off; off >>= 1)
        s += __shfl_xor_sync(0xffffffffu, s, off);
    float inv = 1.f / s;
    #pragma unroll
    for (int k = 0; k < 16; k++) q[lane + 32*k] = vals[k] * inv;
}

// ============================================================
// K4: mid[b,i,h,d] = sum_j adjT[b,h,i,j] * v[b,j,h,d]
// 32i x 64d tiles -> grid (16, 8) = 128 blocks; thread 2x4
// ============================================================
__global__ __launch_bounds__(256) void k4_av()
{
    int bh = blockIdx.y; int b = bh >> 2, h = bh & 3;
    int i0 = blockIdx.x * 32;
    __shared__ float sa[32][68];
    __shared__ float sv[64][68];
    int tid = threadIdx.x;
    int tx = tid & 15, ty = tid >> 4;
    const float* A = g_adjT + (size_t)bh * NN * NN;

    float acc[2][4] = {};
    for (int j0 = 0; j0 < NN; j0 += 64) {
        __syncthreads();
        for (int t = tid; t < 512; t += 256) {
            int r = t >> 4, c = (t & 15) * 4;
            float4 v4 = *(const float4*)&A[(i0 + r)*NN + j0 + c];
            *(float4*)&sa[r][c] = v4;
        }
        for (int t = tid; t < 1024; t += 256) {
            int r = t >> 4, c = (t & 15) * 4;
            float4 v4 = *(const float4*)&g_v[(b*NN + j0 + r)*256 + h*64 + c];
            *(float4*)&sv[r][c] = v4;
        }
        __syncthreads();
        #pragma unroll 8
        for (int j = 0; j < 64; j++) {
            float a0 = sa[ty*2][j], a1 = sa[ty*2 + 1][j];
            float4 v4 = *(const float4*)&sv[j][tx*4];
            acc[0][0] = fmaf(a0, v4.x, acc[0][0]);
            acc[0][1] = fmaf(a0, v4.y, acc[0][1]);
            acc[0][2] = fmaf(a0, v4.z, acc[0][2]);
            acc[0][3] = fmaf(a0, v4.w, acc[0][3]);
            acc[1][0] = fmaf(a1, v4.x, acc[1][0]);
            acc[1][1] = fmaf(a1, v4.y, acc[1][1]);
            acc[1][2] = fmaf(a1, v4.z, acc[1][2]);
            acc[1][3] = fmaf(a1, v4.w, acc[1][3]);
        }
    }
    #pragma unroll
    for (int u = 0; u < 2; u++)
        #pragma unroll
        for (int w = 0; w < 4; w++)
            g_mid[(b*NN + i0 + ty*2 + u)*256 + h*64 + tx*4 + w] = acc[u][w];
}

// ============================================================
// K5: out = LN2( mid@Wo + bo + x )
// grid 128 (8 rows each), block 256.
// Inner loop: float4 smem reads + 8-deep Wo prefetch (MLP=8).
// ============================================================
__global__ __launch_bounds__(256) void k5_out(
    const float* __restrict__ x,  const float* __restrict__ Wo,
    const float* __restrict__ bo, const float* __restrict__ g2,
    const float* __restrict__ bt, float* __restrict__ out)
{
    __shared__ float sm[8][260];
    __shared__ float smu[8], srs[8];
    int row0 = blockIdx.x * 8;
    int tid  = threadIdx.x;

    for (int t = tid; t < 8*256; t += 256)
        sm[t >> 8][t & 255] = g_mid[row0*256 + t];
    __syncthreads();

    int col = tid;
    float acc[8];
    #pragma unroll
    for (int r = 0; r < 8; r++) acc[r] = bo[col];

    const float* Wp = Wo + col;
    float w[8], wn[8];
    #pragma unroll
    for (int u = 0; u < 8; u++) w[u] = Wp[u*256];

    for (int k = 0; k < 256; k += 8) {
        int kn = (k + 8) & 255;
        #pragma unroll
        for (int u = 0; u < 8; u++) wn[u] = Wp[(kn + u)*256];
        #pragma unroll
        for (int r = 0; r < 8; r++) {
            float4 xa = *(const float4*)&sm[r][k];
            float4 xb = *(const float4*)&sm[r][k+4];
            float a = acc[r];
            a = fmaf(xa.x, w[0], a); a = fmaf(xa.y, w[1], a);
            a = fmaf(xa.z, w[2], a); a = fmaf(xa.w, w[3], a);
            a = fmaf(xb.x, w[4], a); a = fmaf(xb.y, w[5], a);
            a = fmaf(xb.z, w[6], a); a = fmaf(xb.w, w[7], a);
            acc[r] = a;
        }
        #pragma unroll
        for (int u = 0; u < 8; u++) w[u] = wn[u];
    }

    #pragma unroll
    for (int r = 0; r < 8; r++) acc[r] += x[(row0 + r)*256 + col];
    __syncthreads();
    #pragma unroll
    for (int r = 0; r < 8; r++) sm[r][col] = acc[r];
    __syncthreads();

    int wid = tid >> 5, lane = tid & 31;
    {
        float a = 0.f, q = 0.f;
        for (int c = lane; c < 256; c += 32) {
            float v = sm[wid][c]; a += v; q = fmaf(v, v, q);
        }
        #pragma unroll
        for (int off = 16; off; off >>= 1) {
            a += __shfl_xor_sync(0xffffffffu, a, off);
            q += __shfl_xor_sync(0xffffffffu, q, off);
        }
        if (lane == 0) {
            float mu = a * (1.f/256.f);
            float var = q * (1.f/256.f) - mu*mu;
            smu[wid] = mu; srs[wid] = rsqrtf(var + 1e-5f);
        }
    }
    __syncthreads();
    float g = g2[col], bb = bt[col];
    #pragma unroll
    for (int r = 0; r < 8; r++)
        out[(row0 + r)*256 + col] = (sm[r][col] - smu[r]) * srs[r] * g + bb;
}

// ============================================================
extern "C" void kernel_launch(void* const* d_in, const int* in_sizes, int n_in,
                              void* d_out, int out_size)
{
    const float* x    = (const float*)d_in[0];
    const float* We   = (const float*)d_in[1];
    const float* be   = (const float*)d_in[2];
    const float* ln1g = (const float*)d_in[3];
    const float* ln1b = (const float*)d_in[4];
    const float* W2   = (const float*)d_in[5];
    const float* b2   = (const float*)d_in[6];
    const float* Wv   = (const float*)d_in[7];
    const float* bv   = (const float*)d_in[8];
    const float* Wo   = (const float*)d_in[9];
    const float* bo   = (const float*)d_in[10];
    const float* ln2g = (const float*)d_in[11];
    const float* ln2b = (const float*)d_in[12];
    float* out = (float*)d_out;

    k1_proj   <<<dim3(64, 3),  256>>>(x, We, be, Wv, bv);
    k2_pair   <<<dim3(128, 4), 256>>>(ln1g, ln1b, W2, b2);
    k3_softmax<<<512,          256>>>();
    k4_av     <<<dim3(16, 8),  256>>>();
    k5_out    <<<128,          256>>>(x, Wo, bo, ln2g, ln2b, out);
}

// round 5
// speedup vs baseline: 1.6616x; 1.0116x over previous
#include <cuda_runtime.h>
#include <math.h>

#define BB   2
#define NN   512
#define CC   256
#define OUTD 256
#define HH   4
#define HD   64
#define ROWS (BB*NN)   // 1024

// ---- scratch (device globals; no allocation allowed) ----
__device__ float g_hi[ROWS*OUTD];
__device__ float g_hj[ROWS*OUTD];
__device__ float g_v [ROWS*OUTD];
__device__ float g_s1i[ROWS];
__device__ float g_s2i[ROWS];
__device__ float g_s1j[ROWS];
__device__ float g_s2j[ROWS];
__device__ float g_logT[BB*HH*NN*NN];   // [b*4+h][i][j] planes, 8 MB
__device__ float g_adjT[BB*HH*NN*NN];   // [b*4+h][i][j] planes, 8 MB
__device__ float g_mid[ROWS*OUTD];

// ---------------- packed f32x2 helpers (Blackwell) ----------------
typedef unsigned long long u64;

__device__ __forceinline__ u64 pk2(float lo, float hi) {
    u64 r; asm("mov.b64 %0,{%1,%2};" : "=l"(r) : "f"(lo), "f"(hi)); return r;
}
__device__ __forceinline__ u64 splat(float x) {
    u64 r; asm("mov.b64 %0,{%1,%1};" : "=l"(r) : "f"(x)); return r;
}
__device__ __forceinline__ void upk(u64 a, float& x, float& y) {
    asm("mov.b64 {%0,%1},%2;" : "=f"(x), "=f"(y) : "l"(a));
}
__device__ __forceinline__ u64 f2add(u64 a, u64 b) {
    u64 d; asm("add.rn.f32x2 %0,%1,%2;" : "=l"(d) : "l"(a), "l"(b)); return d;
}
__device__ __forceinline__ u64 f2mul(u64 a, u64 b) {
    u64 d; asm("mul.rn.f32x2 %0,%1,%2;" : "=l"(d) : "l"(a), "l"(b)); return d;
}
__device__ __forceinline__ u64 f2fma(u64 a, u64 b, u64 c) {
    u64 d; asm("fma.rn.f32x2 %0,%1,%2,%3;" : "=l"(d) : "l"(a), "l"(b), "l"(c)); return d;
}
__device__ __forceinline__ float tanha(float x) {
    float r; asm("tanh.approx.f32 %0,%1;" : "=f"(r) : "f"(x)); return r;
}
__device__ __forceinline__ float ex2a(float x) {
    float r; asm("ex2.approx.f32 %0,%1;" : "=f"(r) : "f"(x)); return r;
}

// ============================================================
// K1: h_i = x@We[:C]+be ; h_j = x@We[C:] ; v = x@Wv+bv
//     + per-row sum / sumsq for h_i, h_j
// grid (64, 3), block 256. float4 smem reads + 8-deep W prefetch.
// ============================================================
__global__ __launch_bounds__(256) void k1_proj(
    const float* __restrict__ x, const float* __restrict__ We,
    const float* __restrict__ be, const float* __restrict__ Wv,
    const float* __restrict__ bv)
{
    __shared__ float sx[16][260];
    int row0 = blockIdx.x * 16;
    int mat  = blockIdx.y;

    for (int t = threadIdx.x; t < 16*256; t += 256)
        sx[t >> 8][t & 255] = x[row0*256 + t];
    __syncthreads();

    int col = threadIdx.x;
    const float* W; float bias; float* out;
    if (mat == 0)      { W = We;           bias = be[col]; out = g_hi; }
    else if (mat == 1) { W = We + 256*256; bias = 0.f;     out = g_hj; }
    else               { W = Wv;           bias = bv[col]; out = g_v;  }

    float acc[16];
    #pragma unroll
    for (int r = 0; r < 16; r++) acc[r] = bias;

    const float* Wp = W + col;
    float w[8], wn[8];
    #pragma unroll
    for (int u = 0; u < 8; u++) w[u] = Wp[u*256];

    for (int k = 0; k < 256; k += 8) {
        int kn = (k + 8) & 255;
        #pragma unroll
        for (int u = 0; u < 8; u++) wn[u] = Wp[(kn + u)*256];
        #pragma unroll
        for (int r = 0; r < 16; r++) {
            float4 xa = *(const float4*)&sx[r][k];
            float4 xb = *(const float4*)&sx[r][k+4];
            float a = acc[r];
            a = fmaf(xa.x, w[0], a); a = fmaf(xa.y, w[1], a);
            a = fmaf(xa.z, w[2], a); a = fmaf(xa.w, w[3], a);
            a = fmaf(xb.x, w[4], a); a = fmaf(xb.y, w[5], a);
            a = fmaf(xb.z, w[6], a); a = fmaf(xb.w, w[7], a);
            acc[r] = a;
        }
        #pragma unroll
        for (int u = 0; u < 8; u++) w[u] = wn[u];
    }
    #pragma unroll
    for (int r = 0; r < 16; r++) out[(row0 + r)*256 + col] = acc[r];

    if (mat < 2) {
        __syncthreads();
        #pragma unroll
        for (int r = 0; r < 16; r++) sx[r][col] = acc[r];
        __syncthreads();
        int wid = threadIdx.x >> 5, lane = threadIdx.x & 31;
        float* s1 = (mat == 0) ? g_s1i : g_s1j;
        float* s2 = (mat == 0) ? g_s2i : g_s2j;
        for (int r = wid; r < 16; r += 8) {
            float a = 0.f, q = 0.f;
            for (int c = lane; c < 256; c += 32) {
                float v = sx[r][c]; a += v; q = fmaf(v, v, q);
            }
            #pragma unroll
            for (int off = 16; off; off >>= 1) {
                a += __shfl_xor_sync(0xffffffffu, a, off);
                q += __shfl_xor_sync(0xffffffffu, q, off);
            }
            if (lane == 0) { s1[row0 + r] = a; s2[row0 + r] = q; }
        }
    }
}

// ============================================================
// K2: dominant pairwise kernel, f32x2-packed; tanh-GELU (MUFU).
// Writes head-separated logit planes [b*4+h][i][j] (coalesced).
// grid (128, 4), block 256; warp = 1 i-row x 32 j-rows
// ============================================================
#define TI 8
#define SJ 258   // 8B-aligned row stride

__global__ __launch_bounds__(256) void k2_pair(
    const float* __restrict__ ln1g, const float* __restrict__ ln1b,
    const float* __restrict__ W2,   const float* __restrict__ b2)
{
    __shared__ float shi[TI][SJ];
    __shared__ float shj[32][SJ];
    __shared__ ulonglong2 sGB[128];            // {(g0,g1),(b0,b1)} per ch-pair
    __shared__ float4 sWa[128], sWb[128];      // h01 / h23 channel-pair packs
    __shared__ float s1i[TI], s2i[TI], s1j[32], s2j[32];
    __shared__ float sb2[4];

    int ri0 = blockIdx.x * TI;
    int b   = ri0 >> 9;
    int ib0 = ri0 & 511;
    int tid = threadIdx.x;

    for (int t = tid; t < TI*256; t += 256)
        shi[t >> 8][t & 255] = g_hi[ri0*256 + t];
    if (tid < 128) {
        sGB[tid].x = pk2(ln1g[2*tid], ln1g[2*tid+1]);
        sGB[tid].y = pk2(ln1b[2*tid], ln1b[2*tid+1]);
        const float* w = W2 + tid*8;   // channels 2t,2t+1 x 4 heads
        sWa[tid] = make_float4(w[0], w[4], w[1], w[5]);
        sWb[tid] = make_float4(w[2], w[6], w[3], w[7]);
    }
    if (tid < TI) { s1i[tid] = g_s1i[ri0 + tid]; s2i[tid] = g_s2i[ri0 + tid]; }
    if (tid < 4)  sb2[tid] = b2[tid];

    int ti = tid >> 5;
    int tj = tid & 31;

    const u64 HALF = splat(0.5f);
    const u64 C0   = splat(0.7978845608028654f);
    const u64 C3   = splat(0.7978845608028654f * 0.044715f);

    for (int jt = 0; jt < 4; jt++) {
        int j0  = blockIdx.y * 128 + jt * 32;
        int rj0 = b * NN + j0;
        __syncthreads();
        for (int t = tid; t < 32*256; t += 256)
            shj[t >> 8][t & 255] = g_hj[rj0*256 + t];
        if (tid < 32) { s1j[tid] = g_s1j[rj0 + tid]; s2j[tid] = g_s2j[rj0 + tid]; }
        __syncthreads();

        // pass A: packed dot(h_i, h_j) for the Var cross term
        u64 dac = splat(0.f);
        #pragma unroll 8
        for (int c2 = 0; c2 < 128; c2++) {
            u64 a = *(const u64*)&shi[ti][2*c2];
            u64 c = *(const u64*)&shj[tj][2*c2];
            dac = f2fma(a, c, dac);
        }
        float dlo, dhi; upk(dac, dlo, dhi);
        float dot = dlo + dhi;

        float mu   = (s1i[ti] + s1j[tj]) * (1.f/256.f);
        float ex2  = (s2i[ti] + s2j[tj] + 2.f*dot) * (1.f/256.f);
        float var  = ex2 - mu*mu;
        float rstd = rsqrtf(var + 1e-5f);
        u64 rstd2 = splat(rstd);
        u64 nmr2  = splat(-mu * rstd);

        u64 acc0 = splat(0.f), acc1 = splat(0.f), acc2 = splat(0.f), acc3 = splat(0.f);
        #pragma unroll 4
        for (int c2 = 0; c2 < 128; c2++) {
            u64 hiv = *(const u64*)&shi[ti][2*c2];
            u64 hjv = *(const u64*)&shj[tj][2*c2];
            u64 e = f2add(hiv, hjv);
            u64 z = f2fma(e, rstd2, nmr2);
            ulonglong2 gb = sGB[c2];
            u64 y = f2fma(z, gb.x, gb.y);

            // gelu_tanh(y) = 0.5*y*(1 + tanh(0.79788456*(y + 0.044715*y^3)))
            u64 y2 = f2mul(y, y);
            u64 t1 = f2fma(y2, C3, C0);
            u64 ar = f2mul(y, t1);
            float al, ah; upk(ar, al, ah);
            u64 th = pk2(tanha(al), tanha(ah));
            u64 u  = f2mul(y, HALF);
            u64 g  = f2fma(u, th, u);

            float4 wa = sWa[c2];
            float4 wb = sWb[c2];
            acc0 = f2fma(g, pk2(wa.x, wa.y), acc0);
            acc1 = f2fma(g, pk2(wa.z, wa.w), acc1);
            acc2 = f2fma(g, pk2(wb.x, wb.y), acc2);
            acc3 = f2fma(g, pk2(wb.z, wb.w), acc3);
        }
        float x0, x1, y0, y1, z0, z1, w0, w1;
        upk(acc0, x0, x1); upk(acc1, y0, y1);
        upk(acc2, z0, z1); upk(acc3, w0, w1);

        // head-separated planes [b*4+h][i][j]; each store coalesced 128B/warp
        size_t base = ((size_t)(b*4)*NN + (ib0 + ti))*NN + (j0 + tj);
        g_logT[base         ] = x0 + x1 + sb2[0];
        g_logT[base + 262144] = y0 + y1 + sb2[1];
        g_logT[base + 524288] = z0 + z1 + sb2[2];
        g_logT[base + 786432] = w0 + w1 + sb2[3];
    }
}

// ============================================================
// K3: softmax over j per plane row; fully contiguous float4 I/O.
// grid 512, block 256 (warp per row of 512)
// ============================================================
__global__ __launch_bounds__(256) void k3_softmax()
{
    int row  = blockIdx.x * 8 + (threadIdx.x >> 5);  // 0..4095 = bh*512 + i
    int lane = threadIdx.x & 31;
    const float4* p = (const float4*)(g_logT + (size_t)row * NN);
    float4*       q = (float4*)(g_adjT + (size_t)row * NN);

    float4 v[4];
    float m = -1e30f;
    #pragma unroll
    for (int u = 0; u < 4; u++) {
        v[u] = p[lane + 32*u];
        m = fmaxf(m, fmaxf(fmaxf(v[u].x, v[u].y), fmaxf(v[u].z, v[u].w)));
    }
    #pragma unroll
    for (int off = 16; off; off >>= 1)
        m = fmaxf(m, __shfl_xor_sync(0xffffffffu, m, off));
    float s = 0.f;
    #pragma unroll
    for (int u = 0; u < 4; u++) {
        v[u].x = ex2a((v[u].x - m)*1.44269504f);
        v[u].y = ex2a((v[u].y - m)*1.44269504f);
        v[u].z = ex2a((v[u].z - m)*1.44269504f);
        v[u].w = ex2a((v[u].w - m)*1.44269504f);
        s += v[u].x + v[u].y + v[u].z + v[u].w;
    }
    #pragma unroll
    for (int off = 16; off; off >>= 1)
        s += __shfl_xor_sync(0xffffffffu, s, off);
    float inv = 1.f / s;
    #pragma unroll
    for (int u = 0; u < 4; u++) {
        v[u].x *= inv; v[u].y *= inv; v[u].z *= inv; v[u].w *= inv;
        q[lane + 32*u] = v[u];
    }
}

// ============================================================
// K4: mid[b,i,h,d] = sum_j adjT[b,h,i,j] * v[b,j,h,d]
// 16i x 64d tiles -> grid (32, 8) = 256 blocks.
// Register-prefetch pipeline: LDG chunk c+1 issued before compute c.
// ============================================================
__global__ __launch_bounds__(256) void k4_av()
{
    int bh = blockIdx.y; int b = bh >> 2, h = bh & 3;
    int i0 = blockIdx.x * 16;
    __shared__ float sa[16*64];
    __shared__ float sv[64*64];
    int tid = threadIdx.x;
    int ty = tid >> 4, tx = tid & 15;
    int lr = tid >> 4, lc = (tid & 15) * 4;   // load coords
    const float* A = g_adjT + (size_t)bh * NN * NN + (size_t)i0 * NN;
    const float* V = g_v + (size_t)(b*NN)*256 + h*64;

    float4 pa, pv0, pv1, pv2, pv3;
    pa  = *(const float4*)&A[lr*NN + lc];
    pv0 = *(const float4*)&V[(     lr)*256 + lc];
    pv1 = *(const float4*)&V[(16 + lr)*256 + lc];
    pv2 = *(const float4*)&V[(32 + lr)*256 + lc];
    pv3 = *(const float4*)&V[(48 + lr)*256 + lc];

    float a0 = 0.f, a1 = 0.f, a2 = 0.f, a3 = 0.f;
    for (int ch = 0; ch < 8; ch++) {
        __syncthreads();
        *(float4*)&sa[lr*64 + lc] = pa;
        *(float4*)&sv[(     lr)*64 + lc] = pv0;
        *(float4*)&sv[(16 + lr)*64 + lc] = pv1;
        *(float4*)&sv[(32 + lr)*64 + lc] = pv2;
        *(float4*)&sv[(48 + lr)*64 + lc] = pv3;
        __syncthreads();
        if (ch < 7) {
            int j0n = (ch + 1) * 64;
            pa  = *(const float4*)&A[lr*NN + j0n + lc];
            pv0 = *(const float4*)&V[(j0n      + lr)*256 + lc];
            pv1 = *(const float4*)&V[(j0n + 16 + lr)*256 + lc];
            pv2 = *(const float4*)&V[(j0n + 32 + lr)*256 + lc];
            pv3 = *(const float4*)&V[(j0n + 48 + lr)*256 + lc];
        }
        #pragma unroll 8
        for (int j = 0; j < 64; j++) {
            float a = sa[ty*64 + j];
            float4 v4 = *(const float4*)&sv[j*64 + tx*4];
            a0 = fmaf(a, v4.x, a0);
            a1 = fmaf(a, v4.y, a1);
            a2 = fmaf(a, v4.z, a2);
            a3 = fmaf(a, v4.w, a3);
        }
    }
    *(float4*)&g_mid[(size_t)(b*NN + i0 + ty)*256 + h*64 + tx*4] =
        make_float4(a0, a1, a2, a3);
}

// ============================================================
// K5: out = LN2( mid@Wo + bo + x )
// grid 128 (8 rows each), block 256. 8-deep Wo prefetch.
// ============================================================
__global__ __launch_bounds__(256) void k5_out(
    const float* __restrict__ x,  const float* __restrict__ Wo,
    const float* __restrict__ bo, const float* __restrict__ g2,
    const float* __restrict__ bt, float* __restrict__ out)
{
    __shared__ float sm[8][260];
    __shared__ float smu[8], srs[8];
    int row0 = blockIdx.x * 8;
    int tid  = threadIdx.x;

    for (int t = tid; t < 8*256; t += 256)
        sm[t >> 8][t & 255] = g_mid[row0*256 + t];
    __syncthreads();

    int col = tid;
    float acc[8];
    #pragma unroll
    for (int r = 0; r < 8; r++) acc[r] = bo[col];

    const float* Wp = Wo + col;
    float w[8], wn[8];
    #pragma unroll
    for (int u = 0; u < 8; u++) w[u] = Wp[u*256];

    for (int k = 0; k < 256; k += 8) {
        int kn = (k + 8) & 255;
        #pragma unroll
        for (int u = 0; u < 8; u++) wn[u] = Wp[(kn + u)*256];
        #pragma unroll
        for (int r = 0; r < 8; r++) {
            float4 xa = *(const float4*)&sm[r][k];
            float4 xb = *(const float4*)&sm[r][k+4];
            float a = acc[r];
            a = fmaf(xa.x, w[0], a); a = fmaf(xa.y, w[1], a);
            a = fmaf(xa.z, w[2], a); a = fmaf(xa.w, w[3], a);
            a = fmaf(xb.x, w[4], a); a = fmaf(xb.y, w[5], a);
            a = fmaf(xb.z, w[6], a); a = fmaf(xb.w, w[7], a);
            acc[r] = a;
        }
        #pragma unroll
        for (int u = 0; u < 8; u++) w[u] = wn[u];
    }

    #pragma unroll
    for (int r = 0; r < 8; r++) acc[r] += x[(row0 + r)*256 + col];
    __syncthreads();
    #pragma unroll
    for (int r = 0; r < 8; r++) sm[r][col] = acc[r];
    __syncthreads();

    int wid = tid >> 5, lane = tid & 31;
    {
        float a = 0.f, q = 0.f;
        for (int c = lane; c < 256; c += 32) {
            float v = sm[wid][c]; a += v; q = fmaf(v, v, q);
        }
        #pragma unroll
        for (int off = 16; off; off >>= 1) {
            a += __shfl_xor_sync(0xffffffffu, a, off);
            q += __shfl_xor_sync(0xffffffffu, q, off);
        }
        if (lane == 0) {
            float mu = a * (1.f/256.f);
            float var = q * (1.f/256.f) - mu*mu;
            smu[wid] = mu; srs[wid] = rsqrtf(var + 1e-5f);
        }
    }
    __syncthreads();
    float g = g2[col], bb = bt[col];
    #pragma unroll
    for (int r = 0; r < 8; r++)
        out[(row0 + r)*256 + col] = (sm[r][col] - smu[r]) * srs[r] * g + bb;
}

// ============================================================
extern "C" void kernel_launch(void* const* d_in, const int* in_sizes, int n_in,
                              void* d_out, int out_size)
{
    const float* x    = (const float*)d_in[0];
    const float* We   = (const float*)d_in[1];
    const float* be   = (const float*)d_in[2];
    const float* ln1g = (const float*)d_in[3];
    const float* ln1b = (const float*)d_in[4];
    const float* W2   = (const float*)d_in[5];
    const float* b2   = (const float*)d_in[6];
    const float* Wv   = (const float*)d_in[7];
    const float* bv   = (const float*)d_in[8];
    const float* Wo   = (const float*)d_in[9];
    const float* bo   = (const float*)d_in[10];
    const float* ln2g = (const float*)d_in[11];
    const float* ln2b = (const float*)d_in[12];
    float* out = (float*)d_out;

    k1_proj   <<<dim3(64, 3),  256>>>(x, We, be, Wv, bv);
    k2_pair   <<<dim3(128, 4), 256>>>(ln1g, ln1b, W2, b2);
    k3_softmax<<<512,          256>>>();
    k4_av     <<<dim3(32, 8),  256>>>();
    k5_out    <<<128,          256>>>(x, Wo, bo, ln2g, ln2b, out);
}